// round 2
// baseline (speedup 1.0000x reference)
#include <cuda_runtime.h>
#include <math.h>

#define N_BOX 3000
#define NTHREADS 1024
#define FULL_MASK 0xFFFFFFFFu

// smem layout: 32 u64 partials, then 6 float arrays [N] (x1,y1,x2,y2,area,score), then int order [N]
#define SMEM_BYTES (32 * 8 + 6 * N_BOX * 4 + N_BOX * 4)

__global__ void __launch_bounds__(NTHREADS, 1)
softnms_kernel(const float* __restrict__ g_boxes,
               const float* __restrict__ g_scores,
               const int*   __restrict__ g_idxs,
               float* __restrict__ out)
{
    extern __shared__ unsigned char smem_raw[];
    unsigned long long* part = (unsigned long long*)smem_raw;   // 32 u64 scratch
    float* sx1 = (float*)(part + 32);
    float* sy1 = sx1 + N_BOX;
    float* sx2 = sy1 + N_BOX;
    float* sy2 = sx2 + N_BOX;
    float* sar = sy2 + N_BOX;
    float* ssc = sar + N_BOX;
    int*   sor = (int*)(ssc + N_BOX);

    const int tid  = threadIdx.x;
    const int lane = tid & 31;
    const int warp = tid >> 5;

    // ---- 1) max_coord = max over all 4N box coords (max is rounding-free) --
    float m = -INFINITY;
    for (int k = tid; k < 4 * N_BOX; k += NTHREADS) m = fmaxf(m, g_boxes[k]);
    #pragma unroll
    for (int o = 16; o; o >>= 1) m = fmaxf(m, __shfl_down_sync(FULL_MASK, m, o));
    if (lane == 0) ((float*)part)[warp] = m;
    __syncthreads();
    if (warp == 0) {
        float v = ((float*)part)[lane];
        #pragma unroll
        for (int o = 16; o; o >>= 1) v = fmaxf(v, __shfl_down_sync(FULL_MASK, v, o));
        if (lane == 0) ((float*)part)[0] = v;
    }
    __syncthreads();
    const float off_scale = __fadd_rn(((float*)part)[0], 1.0f);   // max_coord + 1
    __syncthreads();   // done reusing part as float scratch

    // ---- 2) class-offset boxes (SoA) + areas + scores + order --------------
    // All ops via _rn intrinsics: no FMA contraction, no fast-math rewriting,
    // exact XLA evaluation order: off = idx*scale (1 rounding); coord+off (1 rounding)
    for (int k = tid; k < N_BOX; k += NTHREADS) {
        float off = __fmul_rn((float)g_idxs[k], off_scale);
        float x1 = __fadd_rn(g_boxes[4 * k + 0], off);
        float y1 = __fadd_rn(g_boxes[4 * k + 1], off);
        float x2 = __fadd_rn(g_boxes[4 * k + 2], off);
        float y2 = __fadd_rn(g_boxes[4 * k + 3], off);
        sx1[k] = x1; sy1[k] = y1; sx2[k] = x2; sy2[k] = y2;
        sar[k] = __fmul_rn(__fsub_rn(x2, x1), __fsub_rn(y2, y1));
        ssc[k] = g_scores[k];
        sor[k] = k;
    }
    __syncthreads();

    // ---- 3) sequential soft-NMS --------------------------------------------
    for (int i = 0; i < N_BOX; ++i) {
        // block argmax over slots [i, N). key = (score_bits << 32) | ~k.
        // scores >= 0 so the f32 bit pattern is order-preserving (incl. denormals);
        // ~k breaks exact ties toward the SMALLEST index (jnp.argmax semantics).
        unsigned long long best = 0ULL;
        for (int k = i + tid; k < N_BOX; k += NTHREADS) {
            unsigned long long key =
                ((unsigned long long)__float_as_uint(ssc[k]) << 32) |
                (unsigned int)(~(unsigned int)k);
            if (key > best) best = key;
        }
        #pragma unroll
        for (int o = 16; o; o >>= 1) {
            unsigned long long v = __shfl_down_sync(FULL_MASK, best, o);
            if (v > best) best = v;
        }
        if (lane == 0) part[warp] = best;
        __syncthreads();
        if (warp == 0) {
            unsigned long long v = part[lane];
            #pragma unroll
            for (int o = 16; o; o >>= 1) {
                unsigned long long u = __shfl_down_sync(FULL_MASK, v, o);
                if (u > v) v = u;
            }
            if (lane == 0) {
                int j = (int)(~(unsigned int)(v & 0xFFFFFFFFull));
                if (j != i) {   // swap slots i and j
                    float t;
                    t = sx1[i]; sx1[i] = sx1[j]; sx1[j] = t;
                    t = sy1[i]; sy1[i] = sy1[j]; sy1[j] = t;
                    t = sx2[i]; sx2[i] = sx2[j]; sx2[j] = t;
                    t = sy2[i]; sy2[i] = sy2[j]; sy2[j] = t;
                    t = sar[i]; sar[i] = sar[j]; sar[j] = t;
                    t = ssc[i]; ssc[i] = ssc[j]; ssc[j] = t;
                    int ti = sor[i]; sor[i] = sor[j]; sor[j] = ti;
                }
            }
        }
        __syncthreads();

        // gaussian decay of all later slots vs the selected box.
        // Exact reference arithmetic:
        //   inter = max(x2m-x1M,0)*max(y2m-y1M,0)
        //   iou   = inter / ((area_a + area_b) - inter)
        //   decay = exp( (-(iou*iou)) / 0.5 )        (/0.5 is exact; == *2)
        // iou == 0  =>  decay == exp(-0) == 1 exactly  =>  skip is bit-exact.
        const float bx1 = sx1[i], by1 = sy1[i], bx2 = sx2[i], by2 = sy2[i];
        const float ba  = sar[i];
        for (int k = i + 1 + tid; k < N_BOX; k += NTHREADS) {
            float iw = __fsub_rn(fminf(bx2, sx2[k]), fmaxf(bx1, sx1[k]));
            float ih = __fsub_rn(fminf(by2, sy2[k]), fmaxf(by1, sy1[k]));
            if (iw > 0.0f && ih > 0.0f) {   // different classes never intersect
                float inter = __fmul_rn(iw, ih);
                float denom = __fsub_rn(__fadd_rn(ba, sar[k]), inter);
                float iou   = __fdiv_rn(inter, denom);
                float arg   = __fmul_rn(-__fmul_rn(iou, iou), 2.0f); // == /0.5
                float decay = expf(arg);                             // libdevice __nv_expf
                ssc[k] = __fmul_rn(ssc[k], decay);
            }
        }
        __syncthreads();
    }

    // ---- 4) write outputs: [scores | order | keep_mask] as f32 -------------
    for (int k = tid; k < N_BOX; k += NTHREADS) {
        float s = ssc[k];
        out[k]              = s;
        out[N_BOX + k]      = (float)sor[k];
        out[2 * N_BOX + k]  = (s > 0.05f) ? 1.0f : 0.0f;
    }
}

extern "C" void kernel_launch(void* const* d_in, const int* in_sizes, int n_in,
                              void* d_out, int out_size) {
    (void)in_sizes; (void)n_in; (void)out_size;
    cudaFuncSetAttribute(softnms_kernel,
                         cudaFuncAttributeMaxDynamicSharedMemorySize, SMEM_BYTES);
    softnms_kernel<<<1, NTHREADS, SMEM_BYTES>>>(
        (const float*)d_in[0],
        (const float*)d_in[1],
        (const int*)d_in[2],
        (float*)d_out);
}

// round 3
// speedup vs baseline: 1.0237x; 1.0237x over previous
#include <cuda_runtime.h>
#include <math.h>

#define N_BOX 3000
#define NTHREADS 1024
#define NWARPS (NTHREADS / 32)
#define FULL_MASK 0xFFFFFFFFu

// smem: float4 sbox[N] | float2 sas[N] (area,score) | u64 part[NWARPS] | int sor[N]
#define SMEM_BYTES (16 * N_BOX + 8 * N_BOX + 8 * NWARPS + 4 * N_BOX)

typedef unsigned long long u64;

__global__ void __launch_bounds__(NTHREADS, 1)
softnms_kernel(const float4* __restrict__ g_boxes,
               const float*  __restrict__ g_scores,
               const int*    __restrict__ g_idxs,
               float* __restrict__ out)
{
    extern __shared__ unsigned char smem_raw[];
    float4* sbox = (float4*)smem_raw;
    float2* sas  = (float2*)(sbox + N_BOX);
    u64*    part = (u64*)(sas + N_BOX);
    int*    sor  = (int*)(part + NWARPS);

    const int tid  = threadIdx.x;
    const int lane = tid & 31;
    const int warp = tid >> 5;

    // ---- 1) max_coord over all 4N coords (max is rounding-free) ------------
    const float* gb = (const float*)g_boxes;
    float m = -INFINITY;
    for (int k = tid; k < 4 * N_BOX; k += NTHREADS) m = fmaxf(m, gb[k]);
    #pragma unroll
    for (int o = 16; o; o >>= 1) m = fmaxf(m, __shfl_down_sync(FULL_MASK, m, o));
    if (lane == 0) ((float*)part)[warp] = m;
    __syncthreads();
    if (warp == 0) {
        float v = ((float*)part)[lane];
        #pragma unroll
        for (int o = 16; o; o >>= 1) v = fmaxf(v, __shfl_down_sync(FULL_MASK, v, o));
        if (lane == 0) ((float*)part)[0] = v;
    }
    __syncthreads();
    const float off_scale = __fadd_rn(((float*)part)[0], 1.0f);   // max_coord + 1
    __syncthreads();   // done reusing part as float scratch

    // ---- 2) build offset boxes + areas + scores + order; initial argmax ----
    // Exact XLA order: off = idx*scale (1 rounding); coord+off (1 rounding).
    u64 best = 0ULL;
    for (int k = tid; k < N_BOX; k += NTHREADS) {
        float4 b = g_boxes[k];
        float off = __fmul_rn((float)g_idxs[k], off_scale);
        b.x = __fadd_rn(b.x, off);
        b.y = __fadd_rn(b.y, off);
        b.z = __fadd_rn(b.z, off);
        b.w = __fadd_rn(b.w, off);
        sbox[k] = b;
        float area = __fmul_rn(__fsub_rn(b.z, b.x), __fsub_rn(b.w, b.y));
        float sc = g_scores[k];
        sas[k] = make_float2(area, sc);
        sor[k] = k;
        // key: scores >= 0 so f32 bits are order-preserving; ~k breaks ties
        // toward the SMALLEST slot (jnp.argmax first-occurrence).
        u64 key = ((u64)__float_as_uint(sc) << 32) | (unsigned)(~(unsigned)k);
        if (key > best) best = key;
    }
    #pragma unroll
    for (int o = 16; o; o >>= 1) {
        u64 v = __shfl_down_sync(FULL_MASK, best, o);
        if (v > best) best = v;
    }
    if (lane == 0) part[warp] = best;
    __syncthreads();

    // ---- 3) fused select/swap/decay loop: 1 pass + 2 syncs per iteration ---
    for (int i = 0; i < N_BOX; ++i) {
        // warp 0: reduce the per-warp argmax partials (these cover slots [i,N)
        // of the CURRENT scores), then lanes 0-2 do the swap in parallel.
        if (warp == 0) {
            u64 v = part[lane];
            #pragma unroll
            for (int o = 16; o; o >>= 1) {
                u64 u = __shfl_down_sync(FULL_MASK, v, o);
                if (u > v) v = u;
            }
            v = __shfl_sync(FULL_MASK, v, 0);       // broadcast winner key
            int j = (int)(~(unsigned)(v & 0xFFFFFFFFull));
            if (j != i) {
                if (lane == 0)      { float4 t = sbox[i]; sbox[i] = sbox[j]; sbox[j] = t; }
                else if (lane == 1) { float2 t = sas[i];  sas[i]  = sas[j];  sas[j]  = t; }
                else if (lane == 2) { int    t = sor[i];  sor[i]  = sor[j];  sor[j]  = t; }
            }
        }
        __syncthreads();   // swap visible to all

        // decay slots (i, N) vs box i, and simultaneously compute the argmax
        // of the post-decay scores over slots [i+1, N) -> selection for i+1.
        const float4 bb = sbox[i];
        const float  ba = sas[i].x;
        best = 0ULL;
        for (int k = i + 1 + tid; k < N_BOX; k += NTHREADS) {
            float4 c  = sbox[k];
            float2 as = sas[k];
            float iw = __fsub_rn(fminf(bb.z, c.z), fmaxf(bb.x, c.x));
            float ih = __fsub_rn(fminf(bb.w, c.w), fmaxf(bb.y, c.y));
            float sc = as.y;
            if (iw > 0.0f && ih > 0.0f) {   // iou==0 => decay==1 exactly => skip
                float inter = __fmul_rn(iw, ih);
                float denom = __fsub_rn(__fadd_rn(ba, as.x), inter);
                float iou   = __fdiv_rn(inter, denom);
                float arg   = __fmul_rn(-__fmul_rn(iou, iou), 2.0f); // == /0.5
                sc = __fmul_rn(sc, expf(arg));                       // libdevice expf
                sas[k].y = sc;
            }
            u64 key = ((u64)__float_as_uint(sc) << 32) | (unsigned)(~(unsigned)k);
            if (key > best) best = key;
        }
        #pragma unroll
        for (int o = 16; o; o >>= 1) {
            u64 v = __shfl_down_sync(FULL_MASK, best, o);
            if (v > best) best = v;
        }
        if (lane == 0) part[warp] = best;
        __syncthreads();   // partials visible for next iteration
    }

    // ---- 4) outputs: [scores | order | keep_mask] as f32 -------------------
    for (int k = tid; k < N_BOX; k += NTHREADS) {
        float s = sas[k].y;
        out[k]             = s;
        out[N_BOX + k]     = (float)sor[k];
        out[2 * N_BOX + k] = (s > 0.05f) ? 1.0f : 0.0f;
    }
}

extern "C" void kernel_launch(void* const* d_in, const int* in_sizes, int n_in,
                              void* d_out, int out_size) {
    (void)in_sizes; (void)n_in; (void)out_size;
    cudaFuncSetAttribute(softnms_kernel,
                         cudaFuncAttributeMaxDynamicSharedMemorySize, SMEM_BYTES);
    softnms_kernel<<<1, NTHREADS, SMEM_BYTES>>>(
        (const float4*)d_in[0],
        (const float*)d_in[1],
        (const int*)d_in[2],
        (float*)d_out);
}